// round 14
// baseline (speedup 1.0000x reference)
#include <cuda_runtime.h>

#define B_     8
#define NA_    9
#define NH_    64
#define NW_    64
#define NG_    32
#define NC_    80
#define NANCH  (NA_*NH_*NW_)        // 36864
#define TPB    512
#define BPI    (NANCH/TPB)          // 72 chunks per image
#define NCHNK  (B_*BPI)             // 576 chunks
#define NBLK   (2*NCHNK)            // 1152 blocks: even=stream, odd=anchor
#define NITER  20                   // float4 per anchor (80 classes)
#define NSTG   20                   // 8KB stages per stream chunk (160KB total)
#define RING   4                    // ring depth (32KB dynamic smem)
#define STGB   8192                 // stage bytes
#define STGF4  512                  // float4 per stage (one per thread)
#define LOG2E  1.4426950408889634f
#define LN2    0.6931471805599453f

// per-chunk partials (deterministic reduction, no float atomics)
__device__ float g_cls_s[NCHNK];
__device__ float g_corr [NCHNK];
__device__ float g_xywh [NCHNK];
__device__ float g_npos [NCHNK];
__device__ unsigned int g_count = 0;

__constant__ float c_aw[9] = {
    (float)(32.0*1.0),        (float)(32.0*1.0*1.4),        (float)(32.0*1.0*0.7),
    (float)(32.0*1.2599),     (float)(32.0*1.2599*1.4),     (float)(32.0*1.2599*0.7),
    (float)(32.0*1.5874),     (float)(32.0*1.5874*1.4),     (float)(32.0*1.5874*0.7)
};
__constant__ float c_ah[9] = {
    (float)(32.0*1.0),        (float)(32.0*1.0*0.7),        (float)(32.0*1.0*1.4),
    (float)(32.0*1.2599),     (float)(32.0*1.2599*0.7),     (float)(32.0*1.2599*1.4),
    (float)(32.0*1.5874),     (float)(32.0*1.5874*0.7),     (float)(32.0*1.5874*1.4)
};

__device__ __forceinline__ float ex2f(float x) {
    float y; asm("ex2.approx.f32 %0, %1;" : "=f"(y) : "f"(x)); return y;
}
__device__ __forceinline__ float lg2f(float x) {
    float y; asm("lg2.approx.f32 %0, %1;" : "=f"(y) : "f"(x)); return y;
}
__device__ __forceinline__ unsigned smem_u32(const void* p) {
    return (unsigned)__cvta_generic_to_shared(p);
}
__device__ __forceinline__ void mbar_init(unsigned mb, unsigned cnt) {
    asm volatile("mbarrier.init.shared.b64 [%0], %1;" :: "r"(mb), "r"(cnt) : "memory");
}
__device__ __forceinline__ void mbar_expect_tx(unsigned mb, unsigned bytes) {
    asm volatile("mbarrier.arrive.expect_tx.shared.b64 _, [%0], %1;"
                 :: "r"(mb), "r"(bytes) : "memory");
}
__device__ __forceinline__ void bulk_g2s(unsigned dst, const void* src,
                                         unsigned bytes, unsigned mb) {
    asm volatile("cp.async.bulk.shared::cta.global.mbarrier::complete_tx::bytes "
                 "[%0], [%1], %2, [%3];"
                 :: "r"(dst), "l"(src), "r"(bytes), "r"(mb) : "memory");
}
__device__ __forceinline__ void mbar_wait(unsigned mb, unsigned parity) {
    asm volatile(
        "{\n\t"
        ".reg .pred P;\n\t"
        "WL_%=:\n\t"
        "mbarrier.try_wait.parity.acquire.cta.shared::cta.b64 P, [%0], %1, 0x989680;\n\t"
        "@P bra.uni WD_%=;\n\t"
        "bra.uni WL_%=;\n\t"
        "WD_%=:\n\t"
        "}"
        :: "r"(mb), "r"(parity) : "memory");
}

__global__ void __launch_bounds__(TPB, 4)
retina_fused(const float* __restrict__ t_xywh,
             const float* __restrict__ logits,
             const float* __restrict__ gtb,
             const int*   __restrict__ gtc,
             float* __restrict__ out)
{
    extern __shared__ char dynsm[];   // stream: 32KB TMA ring | anchor: tables
    __shared__ unsigned long long s_mbar[RING];
    __shared__ float  s_red[3][16];
    __shared__ float  s_fin[24];
    __shared__ unsigned int s_last;

    const int bid = blockIdx.x;
    const int rid = bid >> 1;
    const int b   = rid / BPI;
    const int blk = rid % BPI;
    const int tid = threadIdx.x;
    const int lane = tid & 31, wrp = tid >> 5;
    const int n0  = blk * TPB;

    if ((bid & 1) == 0) {
        // ================= STREAM ROLE: TMA-bulk pipelined BCE ===============
        // Bulk-copy engine owns the global->smem path (deep queues, bypasses
        // the per-SM LDG miss-queue). 4-stage 8KB ring; each thread consumes
        // exactly its own float4 per stage.
        float4* ring = (float4*)dynsm;
        const unsigned ring0 = smem_u32(ring);
        const unsigned mb0   = smem_u32(&s_mbar[0]);
        if (tid == 0) {
            #pragma unroll
            for (int j = 0; j < RING; ++j) mbar_init(mb0 + 8u*j, 1u);
            asm volatile("fence.proxy.async.shared::cta;" ::: "memory");
        }
        __syncthreads();

        const char* gsrc = (const char*)logits
                         + (size_t)(b*NANCH + n0) * NC_ * sizeof(float);
        if (tid == 0) {
            #pragma unroll
            for (int s = 0; s < RING; ++s) {
                mbar_expect_tx(mb0 + 8u*s, STGB);
                bulk_g2s(ring0 + s*STGB, gsrc + (size_t)s*STGB, STGB, mb0 + 8u*s);
            }
        }

        float acc_l = 0.0f;
        #pragma unroll
        for (int k = 0; k < NSTG; ++k) {
            const int      sl = k & (RING - 1);
            const unsigned ph = (unsigned)(k / RING) & 1u;
            mbar_wait(mb0 + 8u*sl, ph);
            float4 v = ring[sl*STGF4 + tid];
            __syncthreads();                       // all reads of slot done
            if (k + RING < NSTG && tid == 0) {     // refill the freed slot
                mbar_expect_tx(mb0 + 8u*sl, STGB);
                bulk_g2s(ring0 + sl*STGB, gsrc + (size_t)(k+RING)*STGB,
                         STGB, mb0 + 8u*sl);
            }
            // softplus: two independent 2-deep chains, merged before lg2
            float pa = 1.0f, pb = 1.0f;
            pa = __fmaf_rn(pa, ex2f(LOG2E*v.x), pa);
            pb = __fmaf_rn(pb, ex2f(LOG2E*v.z), pb);
            pa = __fmaf_rn(pa, ex2f(LOG2E*v.y), pa);
            pb = __fmaf_rn(pb, ex2f(LOG2E*v.w), pb);
            acc_l += lg2f(pa * pb);
        }
        #pragma unroll
        for (int o = 16; o; o >>= 1) acc_l += __shfl_down_sync(0xFFFFFFFFu, acc_l, o);
        if (lane == 0) s_red[0][wrp] = acc_l;
        __syncthreads();
        if (wrp == 0 && lane < 16) {
            float v = s_red[0][lane];
            #pragma unroll
            for (int o = 8; o; o >>= 1) v += __shfl_down_sync(0x0000FFFFu, v, o);
            if (lane == 0) g_cls_s[rid] = LN2 * v;
        }
    } else {
        // ================= ANCHOR ROLE: IoU, xywh, corrections ===============
        float*  s_ox  = (float*)dynsm;               // [NG_*64] 8KB
        float*  s_oy  = s_ox + NG_*64;               // [NG_*8]  1KB
        float2* s_c   = (float2*)(s_oy + NG_*8);     // [NG_]
        float*  s_Cg  = (float*)(s_c + NG_);         // [NG_]
        float4* s_tlbr= (float4*)(s_Cg + NG_);       // [NG_]
        float4* s_box = s_tlbr + NG_;
        int*    s_cat = (int*)(s_box + NG_);

        const int a  = n0 >> 12;
        const int h0 = (n0 >> 6) & 63;
        const float aw = c_aw[a], ah = c_ah[a];
        const float areaA = aw * ah;

        if (tid < NG_) {
            float4 g = ((const float4*)gtb)[b*NG_ + tid];
            float hw = 0.5f*g.z, hh = 0.5f*g.w;
            s_tlbr[tid] = make_float4(g.x - hw, g.y - hh, g.x + hw, g.y + hh);
            s_box [tid] = g;
            s_cat [tid] = gtc[b*NG_ + tid];
            float Cg = areaA + g.z * g.w;
            s_c [tid] = make_float2(Cg * (1.0f/3.0f), Cg * (2.0f/7.0f));
            s_Cg[tid] = Cg;
        }
        __syncthreads();

        {   // overlap tables
            const float kl = 4.0f - 0.5f*aw;
            #pragma unroll
            for (int i = 0; i < (NG_*64)/TPB; ++i) {
                int idx = tid + i*TPB;
                int g = idx >> 6, w = idx & 63;
                float wl = fmaf((float)w, 8.0f, kl);
                s_ox[idx] = fmaxf(fminf(wl + aw, s_tlbr[g].z) - fmaxf(wl, s_tlbr[g].x), 0.0f);
            }
            if (tid < NG_*8) {
                int g = tid >> 3, hh = tid & 7;
                float yl = fmaf((float)(h0 + hh), 8.0f, 4.0f - 0.5f*ah);
                s_oy[tid] = fmaxf(fminf(yl + ah, s_tlbr[g].w) - fmaxf(yl, s_tlbr[g].y), 0.0f);
            }
        }
        __syncthreads();

        const int h8 = tid >> 6;
        const int w  = tid & 63;
        const float* oxp = s_ox + w;
        const float* oyp = s_oy + h8;

        float m1 = -1e30f, m2 = -1e30f;
        #pragma unroll 8
        for (int g = 0; g < NG_; ++g) {
            float ox = oxp[g << 6];
            float oy = oyp[g << 3];
            float2 c = s_c[g];
            m1 = fmaxf(m1, fmaf(ox, oy, -c.x));   // >0 <=> IoU>0.5
            m2 = fmaxf(m2, fmaf(ox, oy, -c.y));   // <0 <=> IoU<0.4
        }
        const bool pos = m1 > 0.0f;
        const bool neg = m2 < 0.0f;

        float l_xywh = 0.0f;
        float acc = 0.0f;                 // correction accumulator (ln units)
        if (__any_sync(0xFFFFFFFFu, pos)) {
            float bI = 0.0f, bU = 1.0f; int bG = 0;
            #pragma unroll 4
            for (int g = 0; g < NG_; ++g) {
                float I = oxp[g << 6] * oyp[g << 3];
                float U = s_Cg[g] - I;
                if (I * bU > bI * U) { bI = I; bU = U; bG = g; }
            }
            if (pos) {
                const int n = n0 + tid;
                const int h = h0 + h8;
                const float acx = ((float)w + 0.5f) * 8.0f;
                const float acy = ((float)h + 0.5f) * 8.0f;
                float4 gbx = s_box[bG];
                float tx = (gbx.x - acx) / aw;
                float ty = (gbx.y - acy) / ah;
                float tw = __logf(gbx.z / aw + 1e-8f);
                float th = __logf(gbx.w / ah + 1e-8f);
                float4 t = ((const float4*)t_xywh)[ (size_t)((b*NA_ + a) << 12) + (h << 6) + w ];
                float dx = t.x - tx, dy = t.y - ty, dw = t.z - tw, dh = t.w - th;
                l_xywh = dx*dx + dy*dy + dw*dw + dh*dh;
                acc -= logits[(size_t)(b*NANCH + n)*NC_ + s_cat[bG]];
            }
        }

        // warp-cooperative dead-band correction (~0.8 anchors/warp)
        {
            unsigned int dead = __ballot_sync(0xFFFFFFFFu, !(pos | neg));
            while (dead) {
                int src = __ffs(dead) - 1;
                dead &= dead - 1;
                const float4* lq = (const float4*)logits
                                 + (size_t)(b*NANCH + n0 + (wrp << 5) + src)*(NC_/4);
                if (lane < NITER) {
                    float4 u = lq[lane];
                    float pp = 1.0f;
                    pp = __fmaf_rn(pp, ex2f(LOG2E*u.x), pp);
                    pp = __fmaf_rn(pp, ex2f(LOG2E*u.y), pp);
                    pp = __fmaf_rn(pp, ex2f(LOG2E*u.z), pp);
                    pp = __fmaf_rn(pp, ex2f(LOG2E*u.w), pp);
                    acc -= LN2 * lg2f(pp);
                }
            }
        }

        float v0 = acc, v1 = l_xywh, v2 = pos ? 1.0f : 0.0f;
        #pragma unroll
        for (int o = 16; o; o >>= 1) {
            v0 += __shfl_down_sync(0xFFFFFFFFu, v0, o);
            v1 += __shfl_down_sync(0xFFFFFFFFu, v1, o);
            v2 += __shfl_down_sync(0xFFFFFFFFu, v2, o);
        }
        if (lane == 0) { s_red[0][wrp] = v0; s_red[1][wrp] = v1; s_red[2][wrp] = v2; }
        __syncthreads();
        if (wrp == 0 && lane < 16) {
            v0 = s_red[0][lane]; v1 = s_red[1][lane]; v2 = s_red[2][lane];
            #pragma unroll
            for (int o = 8; o; o >>= 1) {
                v0 += __shfl_down_sync(0x0000FFFFu, v0, o);
                v1 += __shfl_down_sync(0x0000FFFFu, v1, o);
                v2 += __shfl_down_sync(0x0000FFFFu, v2, o);
            }
            if (lane == 0) { g_corr[rid] = v0; g_xywh[rid] = v1; g_npos[rid] = v2; }
        }
    }
    __syncthreads();

    // ---- last-block-done: final deterministic reduction ----
    if (tid == 0) {
        __threadfence();
        s_last = (atomicAdd(&g_count, 1u) == NBLK - 1u);
    }
    __syncthreads();
    if (!s_last) return;
    __threadfence();

    float sx = 0.0f;
    for (int i = tid; i < NCHNK; i += TPB) sx += __ldcg(&g_xywh[i]);
    #pragma unroll
    for (int o = 16; o; o >>= 1) sx += __shfl_down_sync(0xFFFFFFFFu, sx, o);
    if (lane == 0) s_fin[wrp] = sx;

    if (wrp < 8) {
        float sc = 0.0f, sp = 0.0f;
        for (int i = lane; i < BPI; i += 32) {
            sc += __ldcg(&g_cls_s[wrp*BPI + i]) + __ldcg(&g_corr[wrp*BPI + i]);
            sp += __ldcg(&g_npos [wrp*BPI + i]);
        }
        #pragma unroll
        for (int o = 16; o; o >>= 1) {
            sc += __shfl_down_sync(0xFFFFFFFFu, sc, o);
            sp += __shfl_down_sync(0xFFFFFFFFu, sp, o);
        }
        if (lane == 0) s_fin[16 + wrp] = sc / (sp + 1.0f);
    }
    __syncthreads();

    if (tid == 0) {
        float tot = 0.0f;
        #pragma unroll
        for (int i = 0; i < 24; ++i) tot += s_fin[i];
        out[0] = tot * (1.0f / (float)B_);
        g_count = 0;
    }
}

extern "C" void kernel_launch(void* const* d_in, const int* in_sizes, int n_in,
                              void* d_out, int out_size)
{
    const float* t_xywh = (const float*)d_in[0];
    const float* logits = (const float*)d_in[1];
    const float* gtb    = (const float*)d_in[2];
    const int*   gtc    = (const int*)  d_in[3];
    (void)in_sizes; (void)n_in; (void)out_size;

    retina_fused<<<NBLK, TPB, RING*STGB>>>(t_xywh, logits, gtb, gtc, (float*)d_out);
}

// round 15
// speedup vs baseline: 1.0218x; 1.0218x over previous
#include <cuda_runtime.h>

#define B_     8
#define NA_    9
#define NH_    64
#define NW_    64
#define NG_    32
#define NC_    80
#define NANCH  (NA_*NH_*NW_)        // 36864
#define TPB    512
#define BPI    (NANCH/TPB)          // 72 chunks per image
#define NCHNK  (B_*BPI)             // 576 chunks
#define NBLK   (2*NCHNK)            // 1152 blocks: even=stream, odd=anchor
#define NITER  20                   // float4 per anchor (80 classes)
#define LHALF  10                   // float4-iterations done via direct LDG
#define THALF  10                   // 8KB stages done via TMA (stages 10..19)
#define RING   4                    // ring depth (32KB dynamic smem)
#define STGB   8192                 // stage bytes
#define STGF4  512                  // float4 per stage (one per thread)
#define LOG2E  1.4426950408889634f
#define LN2    0.6931471805599453f

// per-chunk partials (deterministic reduction, no float atomics)
__device__ float g_cls_s[NCHNK];
__device__ float g_corr [NCHNK];
__device__ float g_xywh [NCHNK];
__device__ float g_npos [NCHNK];
__device__ unsigned int g_count = 0;

__constant__ float c_aw[9] = {
    (float)(32.0*1.0),        (float)(32.0*1.0*1.4),        (float)(32.0*1.0*0.7),
    (float)(32.0*1.2599),     (float)(32.0*1.2599*1.4),     (float)(32.0*1.2599*0.7),
    (float)(32.0*1.5874),     (float)(32.0*1.5874*1.4),     (float)(32.0*1.5874*0.7)
};
__constant__ float c_ah[9] = {
    (float)(32.0*1.0),        (float)(32.0*1.0*0.7),        (float)(32.0*1.0*1.4),
    (float)(32.0*1.2599),     (float)(32.0*1.2599*0.7),     (float)(32.0*1.2599*1.4),
    (float)(32.0*1.5874),     (float)(32.0*1.5874*0.7),     (float)(32.0*1.5874*1.4)
};

__device__ __forceinline__ float ex2f(float x) {
    float y; asm("ex2.approx.f32 %0, %1;" : "=f"(y) : "f"(x)); return y;
}
__device__ __forceinline__ float lg2f(float x) {
    float y; asm("lg2.approx.f32 %0, %1;" : "=f"(y) : "f"(x)); return y;
}
__device__ __forceinline__ unsigned smem_u32(const void* p) {
    return (unsigned)__cvta_generic_to_shared(p);
}
__device__ __forceinline__ void mbar_init(unsigned mb, unsigned cnt) {
    asm volatile("mbarrier.init.shared.b64 [%0], %1;" :: "r"(mb), "r"(cnt) : "memory");
}
__device__ __forceinline__ void mbar_expect_tx(unsigned mb, unsigned bytes) {
    asm volatile("mbarrier.arrive.expect_tx.shared.b64 _, [%0], %1;"
                 :: "r"(mb), "r"(bytes) : "memory");
}
__device__ __forceinline__ void bulk_g2s(unsigned dst, const void* src,
                                         unsigned bytes, unsigned mb) {
    asm volatile("cp.async.bulk.shared::cta.global.mbarrier::complete_tx::bytes "
                 "[%0], [%1], %2, [%3];"
                 :: "r"(dst), "l"(src), "r"(bytes), "r"(mb) : "memory");
}
__device__ __forceinline__ void mbar_wait(unsigned mb, unsigned parity) {
    asm volatile(
        "{\n\t"
        ".reg .pred P;\n\t"
        "WL_%=:\n\t"
        "mbarrier.try_wait.parity.acquire.cta.shared::cta.b64 P, [%0], %1, 0x989680;\n\t"
        "@P bra.uni WD_%=;\n\t"
        "bra.uni WL_%=;\n\t"
        "WD_%=:\n\t"
        "}"
        :: "r"(mb), "r"(parity) : "memory");
}

__global__ void __launch_bounds__(TPB, 4)
retina_fused(const float* __restrict__ t_xywh,
             const float* __restrict__ logits,
             const float* __restrict__ gtb,
             const int*   __restrict__ gtc,
             float* __restrict__ out)
{
    extern __shared__ char dynsm[];   // stream: 32KB TMA ring | anchor: tables
    __shared__ unsigned long long s_mbar[RING];
    __shared__ float  s_red[3][16];
    __shared__ float  s_fin[24];
    __shared__ unsigned int s_last;

    const int bid = blockIdx.x;
    const int rid = bid >> 1;
    const int b   = rid / BPI;
    const int blk = rid % BPI;
    const int tid = threadIdx.x;
    const int lane = tid & 31, wrp = tid >> 5;
    const int n0  = blk * TPB;

    if ((bid & 1) == 0) {
        // ========== STREAM ROLE: dual-engine (LDG + TMA-bulk) BCE ==========
        // TMA ring prefetches the SECOND half of the chunk while the first
        // half is crunched with direct LDG -> both DRAM paths active at once.
        float4* ring = (float4*)dynsm;
        const unsigned ring0 = smem_u32(ring);
        const unsigned mb0   = smem_u32(&s_mbar[0]);
        if (tid == 0) {
            #pragma unroll
            for (int j = 0; j < RING; ++j) mbar_init(mb0 + 8u*j, 1u);
            asm volatile("fence.proxy.async.shared::cta;" ::: "memory");
        }
        __syncthreads();

        const char* gsrc = (const char*)logits
                         + (size_t)(b*NANCH + n0) * NC_ * sizeof(float);
        if (tid == 0) {   // prefire ring over stages 10..13
            #pragma unroll
            for (int s = 0; s < RING; ++s) {
                mbar_expect_tx(mb0 + 8u*s, STGB);
                bulk_g2s(ring0 + s*STGB, gsrc + (size_t)(LHALF + s)*STGB,
                         STGB, mb0 + 8u*s);
            }
        }

        // ---- first half via direct LDG (TMA streaming concurrently) ----
        const float4* lp = (const float4*)logits + (size_t)(b*NANCH + n0)*(NC_/4);
        float acc_l = 0.0f;
        #pragma unroll
        for (int kk = 0; kk < LHALF; kk += 2) {
            float4 v0 = lp[tid + (kk+0)*TPB];
            float4 v1 = lp[tid + (kk+1)*TPB];
            float pa = 1.0f, pb = 1.0f;
            pa = __fmaf_rn(pa, ex2f(LOG2E*v0.x), pa);
            pb = __fmaf_rn(pb, ex2f(LOG2E*v1.x), pb);
            pa = __fmaf_rn(pa, ex2f(LOG2E*v0.y), pa);
            pb = __fmaf_rn(pb, ex2f(LOG2E*v1.y), pb);
            pa = __fmaf_rn(pa, ex2f(LOG2E*v0.z), pa);
            pb = __fmaf_rn(pb, ex2f(LOG2E*v1.z), pb);
            pa = __fmaf_rn(pa, ex2f(LOG2E*v0.w), pa);
            pb = __fmaf_rn(pb, ex2f(LOG2E*v1.w), pb);
            acc_l += lg2f(pa * pb);
        }

        // ---- second half from the TMA ring (with refills) ----
        #pragma unroll
        for (int j = 0; j < THALF; ++j) {
            const int      sl = j & (RING - 1);
            const unsigned ph = (unsigned)(j / RING) & 1u;
            mbar_wait(mb0 + 8u*sl, ph);
            float4 v = ring[sl*STGF4 + tid];
            __syncthreads();                       // all reads of slot done
            if (j + RING < THALF && tid == 0) {    // refill: stage 14+j
                mbar_expect_tx(mb0 + 8u*sl, STGB);
                bulk_g2s(ring0 + sl*STGB, gsrc + (size_t)(LHALF + RING + j)*STGB,
                         STGB, mb0 + 8u*sl);
            }
            float pa = 1.0f, pb = 1.0f;
            pa = __fmaf_rn(pa, ex2f(LOG2E*v.x), pa);
            pb = __fmaf_rn(pb, ex2f(LOG2E*v.z), pb);
            pa = __fmaf_rn(pa, ex2f(LOG2E*v.y), pa);
            pb = __fmaf_rn(pb, ex2f(LOG2E*v.w), pb);
            acc_l += lg2f(pa * pb);
        }

        #pragma unroll
        for (int o = 16; o; o >>= 1) acc_l += __shfl_down_sync(0xFFFFFFFFu, acc_l, o);
        if (lane == 0) s_red[0][wrp] = acc_l;
        __syncthreads();
        if (wrp == 0 && lane < 16) {
            float v = s_red[0][lane];
            #pragma unroll
            for (int o = 8; o; o >>= 1) v += __shfl_down_sync(0x0000FFFFu, v, o);
            if (lane == 0) g_cls_s[rid] = LN2 * v;
        }
    } else {
        // ================= ANCHOR ROLE: IoU, xywh, corrections ===============
        float*  s_ox  = (float*)dynsm;               // [NG_*64] 8KB
        float*  s_oy  = s_ox + NG_*64;               // [NG_*8]  1KB
        float2* s_c   = (float2*)(s_oy + NG_*8);     // [NG_]
        float*  s_Cg  = (float*)(s_c + NG_);         // [NG_]
        float4* s_tlbr= (float4*)(s_Cg + NG_);       // [NG_]
        float4* s_box = s_tlbr + NG_;
        int*    s_cat = (int*)(s_box + NG_);

        const int a  = n0 >> 12;
        const int h0 = (n0 >> 6) & 63;
        const float aw = c_aw[a], ah = c_ah[a];
        const float areaA = aw * ah;

        if (tid < NG_) {
            float4 g = ((const float4*)gtb)[b*NG_ + tid];
            float hw = 0.5f*g.z, hh = 0.5f*g.w;
            s_tlbr[tid] = make_float4(g.x - hw, g.y - hh, g.x + hw, g.y + hh);
            s_box [tid] = g;
            s_cat [tid] = gtc[b*NG_ + tid];
            float Cg = areaA + g.z * g.w;
            s_c [tid] = make_float2(Cg * (1.0f/3.0f), Cg * (2.0f/7.0f));
            s_Cg[tid] = Cg;
        }
        __syncthreads();

        {   // overlap tables
            const float kl = 4.0f - 0.5f*aw;
            #pragma unroll
            for (int i = 0; i < (NG_*64)/TPB; ++i) {
                int idx = tid + i*TPB;
                int g = idx >> 6, w = idx & 63;
                float wl = fmaf((float)w, 8.0f, kl);
                s_ox[idx] = fmaxf(fminf(wl + aw, s_tlbr[g].z) - fmaxf(wl, s_tlbr[g].x), 0.0f);
            }
            if (tid < NG_*8) {
                int g = tid >> 3, hh = tid & 7;
                float yl = fmaf((float)(h0 + hh), 8.0f, 4.0f - 0.5f*ah);
                s_oy[tid] = fmaxf(fminf(yl + ah, s_tlbr[g].w) - fmaxf(yl, s_tlbr[g].y), 0.0f);
            }
        }
        __syncthreads();

        const int h8 = tid >> 6;
        const int w  = tid & 63;
        const float* oxp = s_ox + w;
        const float* oyp = s_oy + h8;

        float m1 = -1e30f, m2 = -1e30f;
        #pragma unroll 8
        for (int g = 0; g < NG_; ++g) {
            float ox = oxp[g << 6];
            float oy = oyp[g << 3];
            float2 c = s_c[g];
            m1 = fmaxf(m1, fmaf(ox, oy, -c.x));   // >0 <=> IoU>0.5
            m2 = fmaxf(m2, fmaf(ox, oy, -c.y));   // <0 <=> IoU<0.4
        }
        const bool pos = m1 > 0.0f;
        const bool neg = m2 < 0.0f;

        float l_xywh = 0.0f;
        float acc = 0.0f;                 // correction accumulator (ln units)
        if (__any_sync(0xFFFFFFFFu, pos)) {
            float bI = 0.0f, bU = 1.0f; int bG = 0;
            #pragma unroll 4
            for (int g = 0; g < NG_; ++g) {
                float I = oxp[g << 6] * oyp[g << 3];
                float U = s_Cg[g] - I;
                if (I * bU > bI * U) { bI = I; bU = U; bG = g; }
            }
            if (pos) {
                const int n = n0 + tid;
                const int h = h0 + h8;
                const float acx = ((float)w + 0.5f) * 8.0f;
                const float acy = ((float)h + 0.5f) * 8.0f;
                float4 gbx = s_box[bG];
                float tx = (gbx.x - acx) / aw;
                float ty = (gbx.y - acy) / ah;
                float tw = __logf(gbx.z / aw + 1e-8f);
                float th = __logf(gbx.w / ah + 1e-8f);
                float4 t = ((const float4*)t_xywh)[ (size_t)((b*NA_ + a) << 12) + (h << 6) + w ];
                float dx = t.x - tx, dy = t.y - ty, dw = t.z - tw, dh = t.w - th;
                l_xywh = dx*dx + dy*dy + dw*dw + dh*dh;
                acc -= logits[(size_t)(b*NANCH + n)*NC_ + s_cat[bG]];
            }
        }

        // warp-cooperative dead-band correction (~0.8 anchors/warp)
        {
            unsigned int dead = __ballot_sync(0xFFFFFFFFu, !(pos | neg));
            while (dead) {
                int src = __ffs(dead) - 1;
                dead &= dead - 1;
                const float4* lq = (const float4*)logits
                                 + (size_t)(b*NANCH + n0 + (wrp << 5) + src)*(NC_/4);
                if (lane < NITER) {
                    float4 u = lq[lane];
                    float pp = 1.0f;
                    pp = __fmaf_rn(pp, ex2f(LOG2E*u.x), pp);
                    pp = __fmaf_rn(pp, ex2f(LOG2E*u.y), pp);
                    pp = __fmaf_rn(pp, ex2f(LOG2E*u.z), pp);
                    pp = __fmaf_rn(pp, ex2f(LOG2E*u.w), pp);
                    acc -= LN2 * lg2f(pp);
                }
            }
        }

        float v0 = acc, v1 = l_xywh, v2 = pos ? 1.0f : 0.0f;
        #pragma unroll
        for (int o = 16; o; o >>= 1) {
            v0 += __shfl_down_sync(0xFFFFFFFFu, v0, o);
            v1 += __shfl_down_sync(0xFFFFFFFFu, v1, o);
            v2 += __shfl_down_sync(0xFFFFFFFFu, v2, o);
        }
        if (lane == 0) { s_red[0][wrp] = v0; s_red[1][wrp] = v1; s_red[2][wrp] = v2; }
        __syncthreads();
        if (wrp == 0 && lane < 16) {
            v0 = s_red[0][lane]; v1 = s_red[1][lane]; v2 = s_red[2][lane];
            #pragma unroll
            for (int o = 8; o; o >>= 1) {
                v0 += __shfl_down_sync(0x0000FFFFu, v0, o);
                v1 += __shfl_down_sync(0x0000FFFFu, v1, o);
                v2 += __shfl_down_sync(0x0000FFFFu, v2, o);
            }
            if (lane == 0) { g_corr[rid] = v0; g_xywh[rid] = v1; g_npos[rid] = v2; }
        }
    }
    __syncthreads();

    // ---- last-block-done: final deterministic reduction ----
    if (tid == 0) {
        __threadfence();
        s_last = (atomicAdd(&g_count, 1u) == NBLK - 1u);
    }
    __syncthreads();
    if (!s_last) return;
    __threadfence();

    float sx = 0.0f;
    for (int i = tid; i < NCHNK; i += TPB) sx += __ldcg(&g_xywh[i]);
    #pragma unroll
    for (int o = 16; o; o >>= 1) sx += __shfl_down_sync(0xFFFFFFFFu, sx, o);
    if (lane == 0) s_fin[wrp] = sx;

    if (wrp < 8) {
        float sc = 0.0f, sp = 0.0f;
        for (int i = lane; i < BPI; i += 32) {
            sc += __ldcg(&g_cls_s[wrp*BPI + i]) + __ldcg(&g_corr[wrp*BPI + i]);
            sp += __ldcg(&g_npos [wrp*BPI + i]);
        }
        #pragma unroll
        for (int o = 16; o; o >>= 1) {
            sc += __shfl_down_sync(0xFFFFFFFFu, sc, o);
            sp += __shfl_down_sync(0xFFFFFFFFu, sp, o);
        }
        if (lane == 0) s_fin[16 + wrp] = sc / (sp + 1.0f);
    }
    __syncthreads();

    if (tid == 0) {
        float tot = 0.0f;
        #pragma unroll
        for (int i = 0; i < 24; ++i) tot += s_fin[i];
        out[0] = tot * (1.0f / (float)B_);
        g_count = 0;
    }
}

extern "C" void kernel_launch(void* const* d_in, const int* in_sizes, int n_in,
                              void* d_out, int out_size)
{
    const float* t_xywh = (const float*)d_in[0];
    const float* logits = (const float*)d_in[1];
    const float* gtb    = (const float*)d_in[2];
    const int*   gtc    = (const int*)  d_in[3];
    (void)in_sizes; (void)n_in; (void)out_size;

    retina_fused<<<NBLK, TPB, RING*STGB>>>(t_xywh, logits, gtb, gtc, (float*)d_out);
}

// round 16
// speedup vs baseline: 1.0935x; 1.0701x over previous
#include <cuda_runtime.h>

#define B_     8
#define NA_    9
#define NH_    64
#define NW_    64
#define NG_    32
#define NC_    80
#define NANCH  (NA_*NH_*NW_)        // 36864
#define TPB    512
#define BPI    (NANCH/TPB)          // 72 chunks per image
#define NCHNK  (B_*BPI)             // 576 chunks
#define NBLK   (2*NCHNK)            // 1152 blocks: even=stream, odd=anchor
#define NITER  20                   // float4 per anchor (80 classes)
#define LOG2E  1.4426950408889634f
#define LN2    0.6931471805599453f

// per-chunk partials (deterministic reduction, no float atomics)
__device__ float g_cls_s[NCHNK];
__device__ float g_corr [NCHNK];
__device__ float g_xywh [NCHNK];
__device__ float g_npos [NCHNK];
__device__ unsigned int g_count = 0;

__constant__ float c_aw[9] = {
    (float)(32.0*1.0),        (float)(32.0*1.0*1.4),        (float)(32.0*1.0*0.7),
    (float)(32.0*1.2599),     (float)(32.0*1.2599*1.4),     (float)(32.0*1.2599*0.7),
    (float)(32.0*1.5874),     (float)(32.0*1.5874*1.4),     (float)(32.0*1.5874*0.7)
};
__constant__ float c_ah[9] = {
    (float)(32.0*1.0),        (float)(32.0*1.0*0.7),        (float)(32.0*1.0*1.4),
    (float)(32.0*1.2599),     (float)(32.0*1.2599*0.7),     (float)(32.0*1.2599*1.4),
    (float)(32.0*1.5874),     (float)(32.0*1.5874*0.7),     (float)(32.0*1.5874*1.4)
};

__device__ __forceinline__ float ex2f(float x) {
    float y; asm("ex2.approx.f32 %0, %1;" : "=f"(y) : "f"(x)); return y;
}
__device__ __forceinline__ float lg2f(float x) {
    float y; asm("lg2.approx.f32 %0, %1;" : "=f"(y) : "f"(x)); return y;
}
// packed f32x2 multiply: both operands are register pairs (free aliasing for
// float4 halves out of LDG.128); one instruction replaces two FMULs.
__device__ __forceinline__ void mul2(float& lo, float& hi, float a_lo, float a_hi,
                                     unsigned long long k2) {
    unsigned long long a, r;
    asm("mov.b64 %0, {%1, %2};" : "=l"(a) : "f"(a_lo), "f"(a_hi));
    asm("mul.rn.f32x2 %0, %1, %2;" : "=l"(r) : "l"(a), "l"(k2));
    asm("mov.b64 {%0, %1}, %2;" : "=f"(lo), "=f"(hi) : "l"(r));
}

__global__ void __launch_bounds__(TPB, 4)
retina_fused(const float* __restrict__ t_xywh,
             const float* __restrict__ logits,
             const float* __restrict__ gtb,
             const int*   __restrict__ gtc,
             float* __restrict__ out)
{
    __shared__ float  s_ox[NG_*64];   // anchor role only (8KB)
    __shared__ float  s_oy[NG_*8];
    __shared__ float2 s_c  [NG_];
    __shared__ float  s_Cg [NG_];
    __shared__ float4 s_tlbr[NG_];
    __shared__ float4 s_box [NG_];
    __shared__ int    s_cat [NG_];
    __shared__ float  s_red[3][16];
    __shared__ float  s_fin[24];
    __shared__ unsigned int s_last;

    const int bid = blockIdx.x;
    const int rid = bid >> 1;           // chunk id 0..575
    const int b   = rid / BPI;
    const int blk = rid % BPI;
    const int tid = threadIdx.x;
    const int lane = tid & 31, wrp = tid >> 5;
    const int n0  = blk * TPB;

    if ((bid & 1) == 0) {
        // ================= STREAM ROLE: pure unmasked BCE sweep ==============
        // softplus(x) = ln2 * lg2(1 + 2^(log2e*x)); packed f32x2 scaling and
        // four independent 2-deep product chains, merged pairwise before one
        // lg2 (product <= 2^70, fp32-safe).
        unsigned long long k2;
        asm("mov.b64 %0, {%1, %1};" : "=l"(k2) : "f"(LOG2E));
        const float4* lp = (const float4*)logits + (size_t)(b*NANCH + n0)*(NC_/4);
        float acc_l = 0.0f;
        #pragma unroll
        for (int kk = 0; kk < NITER; kk += 2) {
            float4 v0 = lp[tid + (kk+0)*TPB];
            float4 v1 = lp[tid + (kk+1)*TPB];
            float s0, s1, s2, s3, s4, s5, s6, s7;
            mul2(s0, s1, v0.x, v0.y, k2);
            mul2(s2, s3, v0.z, v0.w, k2);
            mul2(s4, s5, v1.x, v1.y, k2);
            mul2(s6, s7, v1.z, v1.w, k2);
            float pa = 1.0f, pb = 1.0f, pc = 1.0f, pd = 1.0f;
            pa = __fmaf_rn(pa, ex2f(s0), pa);
            pb = __fmaf_rn(pb, ex2f(s2), pb);
            pc = __fmaf_rn(pc, ex2f(s4), pc);
            pd = __fmaf_rn(pd, ex2f(s6), pd);
            pa = __fmaf_rn(pa, ex2f(s1), pa);
            pb = __fmaf_rn(pb, ex2f(s3), pb);
            pc = __fmaf_rn(pc, ex2f(s5), pc);
            pd = __fmaf_rn(pd, ex2f(s7), pd);
            acc_l += lg2f((pa * pb) * (pc * pd));
        }
        #pragma unroll
        for (int o = 16; o; o >>= 1) acc_l += __shfl_down_sync(0xFFFFFFFFu, acc_l, o);
        if (lane == 0) s_red[0][wrp] = acc_l;
        __syncthreads();
        if (wrp == 0 && lane < 16) {
            float v = s_red[0][lane];
            #pragma unroll
            for (int o = 8; o; o >>= 1) v += __shfl_down_sync(0x0000FFFFu, v, o);
            if (lane == 0) g_cls_s[rid] = LN2 * v;
        }
    } else {
        // ================= ANCHOR ROLE: IoU, xywh, corrections ===============
        const int a  = n0 >> 12;
        const int h0 = (n0 >> 6) & 63;
        const float aw = c_aw[a], ah = c_ah[a];
        const float areaA = aw * ah;

        if (tid < NG_) {
            float4 g = ((const float4*)gtb)[b*NG_ + tid];
            float hw = 0.5f*g.z, hh = 0.5f*g.w;
            s_tlbr[tid] = make_float4(g.x - hw, g.y - hh, g.x + hw, g.y + hh);
            s_box [tid] = g;
            s_cat [tid] = gtc[b*NG_ + tid];
            float Cg = areaA + g.z * g.w;
            s_c [tid] = make_float2(Cg * (1.0f/3.0f), Cg * (2.0f/7.0f));
            s_Cg[tid] = Cg;
        }
        __syncthreads();

        {   // overlap tables
            const float kl = 4.0f - 0.5f*aw;
            #pragma unroll
            for (int i = 0; i < (NG_*64)/TPB; ++i) {
                int idx = tid + i*TPB;
                int g = idx >> 6, w = idx & 63;
                float wl = fmaf((float)w, 8.0f, kl);
                s_ox[idx] = fmaxf(fminf(wl + aw, s_tlbr[g].z) - fmaxf(wl, s_tlbr[g].x), 0.0f);
            }
            if (tid < NG_*8) {
                int g = tid >> 3, hh = tid & 7;
                float yl = fmaf((float)(h0 + hh), 8.0f, 4.0f - 0.5f*ah);
                s_oy[tid] = fmaxf(fminf(yl + ah, s_tlbr[g].w) - fmaxf(yl, s_tlbr[g].y), 0.0f);
            }
        }
        __syncthreads();

        const int h8 = tid >> 6;
        const int w  = tid & 63;
        const float* oxp = s_ox + w;
        const float* oyp = s_oy + h8;

        float m1 = -1e30f, m2 = -1e30f;
        #pragma unroll 8
        for (int g = 0; g < NG_; ++g) {
            float ox = oxp[g << 6];
            float oy = oyp[g << 3];
            float2 c = s_c[g];
            m1 = fmaxf(m1, fmaf(ox, oy, -c.x));   // >0 <=> IoU>0.5
            m2 = fmaxf(m2, fmaf(ox, oy, -c.y));   // <0 <=> IoU<0.4
        }
        const bool pos = m1 > 0.0f;
        const bool neg = m2 < 0.0f;

        float l_xywh = 0.0f;
        float acc = 0.0f;                 // correction accumulator (ln units)
        if (__any_sync(0xFFFFFFFFu, pos)) {
            float bI = 0.0f, bU = 1.0f; int bG = 0;
            #pragma unroll 4
            for (int g = 0; g < NG_; ++g) {
                float I = oxp[g << 6] * oyp[g << 3];
                float U = s_Cg[g] - I;
                if (I * bU > bI * U) { bI = I; bU = U; bG = g; }
            }
            if (pos) {
                const int n = n0 + tid;
                const int h = h0 + h8;
                const float acx = ((float)w + 0.5f) * 8.0f;
                const float acy = ((float)h + 0.5f) * 8.0f;
                float4 gbx = s_box[bG];
                float tx = (gbx.x - acx) / aw;
                float ty = (gbx.y - acy) / ah;
                float tw = __logf(gbx.z / aw + 1e-8f);
                float th = __logf(gbx.w / ah + 1e-8f);
                float4 t = ((const float4*)t_xywh)[ (size_t)((b*NA_ + a) << 12) + (h << 6) + w ];
                float dx = t.x - tx, dy = t.y - ty, dw = t.z - tw, dh = t.w - th;
                l_xywh = dx*dx + dy*dy + dw*dw + dh*dh;
                acc -= logits[(size_t)(b*NANCH + n)*NC_ + s_cat[bG]];
            }
        }

        // warp-cooperative dead-band correction (~0.8 anchors/warp)
        {
            unsigned int dead = __ballot_sync(0xFFFFFFFFu, !(pos | neg));
            while (dead) {
                int src = __ffs(dead) - 1;
                dead &= dead - 1;
                const float4* lq = (const float4*)logits
                                 + (size_t)(b*NANCH + n0 + (wrp << 5) + src)*(NC_/4);
                if (lane < NITER) {
                    float4 u = lq[lane];
                    float pp = 1.0f;
                    pp = __fmaf_rn(pp, ex2f(LOG2E*u.x), pp);
                    pp = __fmaf_rn(pp, ex2f(LOG2E*u.y), pp);
                    pp = __fmaf_rn(pp, ex2f(LOG2E*u.z), pp);
                    pp = __fmaf_rn(pp, ex2f(LOG2E*u.w), pp);
                    acc -= LN2 * lg2f(pp);
                }
            }
        }

        float v0 = acc, v1 = l_xywh, v2 = pos ? 1.0f : 0.0f;
        #pragma unroll
        for (int o = 16; o; o >>= 1) {
            v0 += __shfl_down_sync(0xFFFFFFFFu, v0, o);
            v1 += __shfl_down_sync(0xFFFFFFFFu, v1, o);
            v2 += __shfl_down_sync(0xFFFFFFFFu, v2, o);
        }
        if (lane == 0) { s_red[0][wrp] = v0; s_red[1][wrp] = v1; s_red[2][wrp] = v2; }
        __syncthreads();
        if (wrp == 0 && lane < 16) {
            v0 = s_red[0][lane]; v1 = s_red[1][lane]; v2 = s_red[2][lane];
            #pragma unroll
            for (int o = 8; o; o >>= 1) {
                v0 += __shfl_down_sync(0x0000FFFFu, v0, o);
                v1 += __shfl_down_sync(0x0000FFFFu, v1, o);
                v2 += __shfl_down_sync(0x0000FFFFu, v2, o);
            }
            if (lane == 0) { g_corr[rid] = v0; g_xywh[rid] = v1; g_npos[rid] = v2; }
        }
    }
    __syncthreads();

    // ---- last-block-done: final deterministic reduction ----
    if (tid == 0) {
        __threadfence();
        s_last = (atomicAdd(&g_count, 1u) == NBLK - 1u);
    }
    __syncthreads();
    if (!s_last) return;
    __threadfence();

    float sx = 0.0f;
    for (int i = tid; i < NCHNK; i += TPB) sx += __ldcg(&g_xywh[i]);
    #pragma unroll
    for (int o = 16; o; o >>= 1) sx += __shfl_down_sync(0xFFFFFFFFu, sx, o);
    if (lane == 0) s_fin[wrp] = sx;

    if (wrp < 8) {
        float sc = 0.0f, sp = 0.0f;
        for (int i = lane; i < BPI; i += 32) {
            sc += __ldcg(&g_cls_s[wrp*BPI + i]) + __ldcg(&g_corr[wrp*BPI + i]);
            sp += __ldcg(&g_npos [wrp*BPI + i]);
        }
        #pragma unroll
        for (int o = 16; o; o >>= 1) {
            sc += __shfl_down_sync(0xFFFFFFFFu, sc, o);
            sp += __shfl_down_sync(0xFFFFFFFFu, sp, o);
        }
        if (lane == 0) s_fin[16 + wrp] = sc / (sp + 1.0f);
    }
    __syncthreads();

    if (tid == 0) {
        float tot = 0.0f;
        #pragma unroll
        for (int i = 0; i < 24; ++i) tot += s_fin[i];
        out[0] = tot * (1.0f / (float)B_);
        g_count = 0;
    }
}

extern "C" void kernel_launch(void* const* d_in, const int* in_sizes, int n_in,
                              void* d_out, int out_size)
{
    const float* t_xywh = (const float*)d_in[0];
    const float* logits = (const float*)d_in[1];
    const float* gtb    = (const float*)d_in[2];
    const int*   gtc    = (const int*)  d_in[3];
    (void)in_sizes; (void)n_in; (void)out_size;

    retina_fused<<<NBLK, TPB>>>(t_xywh, logits, gtb, gtc, (float*)d_out);
}